// round 8
// baseline (speedup 1.0000x reference)
#include <cuda_runtime.h>
#include <cuda_fp16.h>

// ---------------- problem constants ----------------
#define NMAX 50000
#define EMAX 800000
#define MKER 27            // 3^3 spline kernels
#define C    64            // hidden channels
#define PLANE ((size_t)NMAX * C)   // one m-plane of y (halves)
#define SSTR 108           // 27 * 4 (ci0,ci1,ci2,pad) layer-0 agg row

// ---------------- static scratch ----------------
// y is PLANE-MAJOR: g_y[m*PLANE + n*C + co]. Every writer/reader streams it.
__device__ __half g_y[(size_t)MKER * PLANE];  // 172.8 MB transformed features
__device__ __half g_msg[(size_t)EMAX * C];    // 102.4 MB per-edge messages (fp16)
__device__ float  g_root[NMAX * C];           // fp32 root-weight term h @ Wr
__device__ float  g_h[NMAX * C];              // hidden state (fp32)
__device__ float  g_S[NMAX * SSTR];           // layer-0 input-space agg (21.6 MB)
__device__ float4 g_srec[EMAX];               // src-CSR records: (dst_slot, ea0, ea1, ea2)
__device__ int    g_rowptr_d[NMAX + 1];       // dst CSR offsets (msg layout / deg)
__device__ int    g_rowptr_s[NMAX + 1];       // src CSR offsets
__device__ int    g_cursor_d[NMAX];
__device__ int    g_cursor_s[NMAX];
__device__ int    g_deg_d[NMAX];
__device__ int    g_deg_s[NMAX];

// ---------------- helpers ----------------
__device__ __forceinline__ float2 ffma2(float2 a, float2 b, float2 c) {
    float2 d;
    asm("fma.rn.f32x2 %0, %1, %2, %3;"
        : "=l"(*reinterpret_cast<unsigned long long*>(&d))
        : "l"(*reinterpret_cast<unsigned long long*>(&a)),
          "l"(*reinterpret_cast<unsigned long long*>(&b)),
          "l"(*reinterpret_cast<unsigned long long*>(&c)));
    return d;
}

__device__ __forceinline__ void basis8(float e0, float e1, float e2,
                                       float w[8], int kk[8]) {
    float p0 = e0 * 2.0f, p1 = e1 * 2.0f, p2 = e2 * 2.0f;
    float f0 = fminf(fmaxf(floorf(p0), 0.f), 1.f);
    float f1 = fminf(fmaxf(floorf(p1), 0.f), 1.f);
    float f2 = fminf(fmaxf(floorf(p2), 0.f), 1.f);
    float u0 = p0 - f0, u1 = p1 - f1, u2 = p2 - f2;
    int base = (int)f0 + 3 * (int)f1 + 9 * (int)f2;
#pragma unroll
    for (int b = 0; b < 8; b++) {
        float a0 = (b & 1) ? u0 : 1.f - u0;
        float a1 = (b & 2) ? u1 : 1.f - u1;
        float a2 = (b & 4) ? u2 : 1.f - u2;
        w[b]  = a0 * a1 * a2;
        kk[b] = base + (b & 1) + 3 * ((b >> 1) & 1) + 9 * ((b >> 2) & 1);
    }
}

// 3-tap linear B-spline basis per dim
__device__ __forceinline__ void basis3(float e, float d[3]) {
    float p = e * 2.0f;
    float f = fminf(fmaxf(floorf(p), 0.f), 1.f);
    float u = p - f;
    bool hi = (f > 0.5f);
    d[0] = hi ? 0.f : 1.f - u;
    d[1] = hi ? 1.f - u : u;
    d[2] = hi ? u : 0.f;
}

// ---------------- prepass ----------------
__global__ void zeroAll_kernel(int N) {
    int i = blockIdx.x * blockDim.x + threadIdx.x;
    if (i < N * SSTR) g_S[i] = 0.f;
    if (i < N) { g_deg_d[i] = 0; g_deg_s[i] = 0; }
}
__global__ void hist2_kernel(const int* __restrict__ src,
                             const int* __restrict__ dst, int E) {
    int i = blockIdx.x * blockDim.x + threadIdx.x;
    if (i < E) {
        atomicAdd(&g_deg_d[dst[i]], 1);
        atomicAdd(&g_deg_s[src[i]], 1);
    }
}
// two-block exclusive scan: block 0 -> dst arrays, block 1 -> src arrays
__global__ void scan2_kernel(int N) {
    __shared__ int ssum[1024];
    int* deg    = blockIdx.x ? g_deg_s    : g_deg_d;
    int* rowptr = blockIdx.x ? g_rowptr_s : g_rowptr_d;
    int* cursor = blockIdx.x ? g_cursor_s : g_cursor_d;
    int tid = threadIdx.x;
    int chunk = (N + 1023) / 1024;
    int beg = tid * chunk;
    int end = min(beg + chunk, N);
    int s = 0;
    for (int i = beg; i < end; i++) s += deg[i];
    ssum[tid] = s;
    __syncthreads();
    for (int off = 1; off < 1024; off <<= 1) {
        int v = 0;
        if (tid >= off) v = ssum[tid - off];
        __syncthreads();
        if (tid >= off) ssum[tid] += v;
        __syncthreads();
    }
    int run = (tid == 0) ? 0 : ssum[tid - 1];
    for (int i = beg; i < end; i++) {
        rowptr[i] = run;
        cursor[i] = run;
        run += deg[i];
    }
    if (tid == 1023) rowptr[N] = ssum[1023];
}

// edge pass: src-CSR record with dst-slot + layer-0 input-space scatter
__global__ void build_kernel(const int* __restrict__ src,
                             const int* __restrict__ dst,
                             const float* __restrict__ ea,
                             const float* __restrict__ x, int E) {
    int e = blockIdx.x * blockDim.x + threadIdx.x;
    if (e >= E) return;
    int s = src[e], d = dst[e];
    float e0 = ea[3 * e], e1 = ea[3 * e + 1], e2 = ea[3 * e + 2];

    int pd = atomicAdd(&g_cursor_d[d], 1);      // slot in msg (dst-grouped)
    int ps = atomicAdd(&g_cursor_s[s], 1);      // position in src order
    g_srec[ps] = make_float4(__int_as_float(pd), e0, e1, e2);

    float w[8]; int kk[8];
    basis8(e0, e1, e2, w, kk);
    float x0 = __ldg(x + 3 * s), x1 = __ldg(x + 3 * s + 1), x2 = __ldg(x + 3 * s + 2);
    float4* Sb = (float4*)(g_S + (size_t)d * SSTR);
#pragma unroll
    for (int c = 0; c < 8; c++)
        atomicAdd(Sb + kk[c], make_float4(w[c] * x0, w[c] * x1, w[c] * x2, 0.f));
}

// ---------------- layer 0 finalize: h = relu(S@W0/deg + x@root0 + b0) --------
__global__ void __launch_bounds__(256)
l0_kernel(const float* __restrict__ x, const float* __restrict__ W0,
          const float* __restrict__ root0, const float* __restrict__ b0, int N) {
    int n    = (blockIdx.x * blockDim.x + threadIdx.x) >> 5;
    int lane = threadIdx.x & 31;
    if (n >= N) return;
    const float* Sr = g_S + (size_t)n * SSTR;
    float sA = Sr[lane];
    float sB = Sr[32 + lane];
    float sC = Sr[64 + lane];
    float sD = (lane < 12) ? Sr[96 + lane] : 0.f;

    float2 acc = make_float2(0.f, 0.f);
#pragma unroll
    for (int m = 0; m < MKER; m++) {
#pragma unroll
        for (int ci = 0; ci < 3; ci++) {
            int s  = m * 4 + ci;
            int r  = s >> 5, sl = s & 31;
            float v = (r == 0) ? __shfl_sync(0xffffffffu, sA, sl)
                    : (r == 1) ? __shfl_sync(0xffffffffu, sB, sl)
                    : (r == 2) ? __shfl_sync(0xffffffffu, sC, sl)
                               : __shfl_sync(0xffffffffu, sD, sl);
            float2 wv = __ldg((const float2*)(W0 + (m * 3 + ci) * C) + lane);
            acc.x += v * wv.x;
            acc.y += v * wv.y;
        }
    }
    int   dg  = g_rowptr_d[n + 1] - g_rowptr_d[n];
    float inv = 1.f / (float)(dg > 0 ? dg : 1);
    float xv  = (lane < 3) ? __ldg(x + 3 * n + lane) : 0.f;
    float x0  = __shfl_sync(0xffffffffu, xv, 0);
    float x1  = __shfl_sync(0xffffffffu, xv, 1);
    float x2  = __shfl_sync(0xffffffffu, xv, 2);
    float2 r0 = __ldg((const float2*)(root0)         + lane);
    float2 r1 = __ldg((const float2*)(root0 + C)     + lane);
    float2 r2 = __ldg((const float2*)(root0 + 2 * C) + lane);
    float2 bb = __ldg((const float2*)(b0)            + lane);
    float2 res;
    res.x = fmaxf(acc.x * inv + x0 * r0.x + x1 * r1.x + x2 * r2.x + bb.x, 0.f);
    res.y = fmaxf(acc.y * inv + x0 * r0.y + x1 * r1.y + x2 * r2.y + bb.y, 0.f);
    ((float2*)g_h)[(size_t)n * 32 + lane] = res;
}

// ---------------- transform: y[m][n][co] = sum_ci h[n,ci] * W[m,ci,co] -------
// Plane-major store: one block writes 64 consecutive nodes of one m-plane
// -> 8 KB fully sequential.
#define T_NODES 64
#define WT_STR  68
__global__ void __launch_bounds__(256)
transform_kernel(const float* __restrict__ h, const float* __restrict__ W,
                 const float* __restrict__ Wr, int N) {
    __shared__ float Wt[C * WT_STR];
    __shared__ float hs[T_NODES * C];
    int m   = blockIdx.y;
    int n0  = blockIdx.x * T_NODES;
    int tid = threadIdx.x;

    const float* Wm = (m < MKER) ? (W + m * C * C) : Wr;
    for (int i = tid; i < C * C; i += 256) {
        int ci = i >> 6, co = i & 63;
        Wt[co * WT_STR + ci] = Wm[i];
    }
    for (int i = tid; i < T_NODES * C; i += 256) {
        int n = n0 + (i >> 6);
        hs[i] = (n < N) ? h[(size_t)n * C + (i & 63)] : 0.f;
    }
    __syncthreads();

    int co0 = (tid & 31) * 2;
    int nb  = (tid >> 5) * 8;

    float2 acc[8][2];
#pragma unroll
    for (int j = 0; j < 8; j++) {
        acc[j][0] = make_float2(0.f, 0.f);
        acc[j][1] = make_float2(0.f, 0.f);
    }

#pragma unroll
    for (int ci = 0; ci < C; ci += 4) {
        float4 wa = *(const float4*)&Wt[co0 * WT_STR + ci];
        float4 wb = *(const float4*)&Wt[(co0 + 1) * WT_STR + ci];
        float2 wa01 = make_float2(wa.x, wa.y), wa23 = make_float2(wa.z, wa.w);
        float2 wb01 = make_float2(wb.x, wb.y), wb23 = make_float2(wb.z, wb.w);
#pragma unroll
        for (int j = 0; j < 8; j++) {
            float4 hv = *(const float4*)&hs[(nb + j) * C + ci];
            float2 h01 = make_float2(hv.x, hv.y), h23 = make_float2(hv.z, hv.w);
            acc[j][0] = ffma2(h01, wa01, acc[j][0]);
            acc[j][0] = ffma2(h23, wa23, acc[j][0]);
            acc[j][1] = ffma2(h01, wb01, acc[j][1]);
            acc[j][1] = ffma2(h23, wb23, acc[j][1]);
        }
    }

#pragma unroll
    for (int j = 0; j < 8; j++) {
        int n = n0 + nb + j;
        if (n >= N) break;
        float v0 = acc[j][0].x + acc[j][0].y;
        float v1 = acc[j][1].x + acc[j][1].y;
        if (m < MKER) {
            __half2* yp = (__half2*)(g_y + (size_t)m * PLANE + (size_t)n * C + co0);
            *yp = __floats2half2_rn(v0, v1);
        } else {
            *(float2*)(g_root + (size_t)n * C + co0) = make_float2(v0, v1);
        }
    }
}

// ---------------- phase A: warp per SRC node ----------------
// Read the node's 27 plane rows (each plane streamed across warps), emit one
// fp16 message per out-edge to its dst-grouped slot (fire-and-forget stores).
__global__ void __launch_bounds__(256)
phaseA_kernel(int N) {
    __shared__ float4 recs[8][32];
    int wid  = threadIdx.x >> 5;
    int lane = threadIdx.x & 31;
    int s    = (blockIdx.x * blockDim.x + threadIdx.x) >> 5;
    if (s >= N) return;
    int beg = g_rowptr_s[s], end = g_rowptr_s[s + 1];
    if (beg == end) return;

    float2 f[MKER];
    const __half2* yb = (const __half2*)(g_y + (size_t)s * C) + lane;
#pragma unroll
    for (int m = 0; m < MKER; m++)
        f[m] = __half22float2(__ldg(yb + m * (PLANE / 2)));

    for (int base = beg; base < end; base += 32) {
        int cnt = min(32, end - base);
        __syncwarp();
        if (lane < cnt) recs[wid][lane] = __ldg(&g_srec[base + lane]);
        __syncwarp();
        for (int e = 0; e < cnt; e++) {
            float4 r = recs[wid][e];
            float d0[3], d1[3], d2[3];
            basis3(r.y, d0); basis3(r.z, d1); basis3(r.w, d2);
            float2 msg = make_float2(0.f, 0.f);
#pragma unroll
            for (int c2 = 0; c2 < 3; c2++) {
#pragma unroll
                for (int c1 = 0; c1 < 3; c1++) {
                    float d12 = d1[c1] * d2[c2];
#pragma unroll
                    for (int c0 = 0; c0 < 3; c0++) {
                        float w = d0[c0] * d12;
                        int m = c0 + 3 * c1 + 9 * c2;
                        msg.x += w * f[m].x;
                        msg.y += w * f[m].y;
                    }
                }
            }
            int slot = __float_as_int(r.x);
            ((__half2*)g_msg)[(size_t)slot * 32 + lane] = __floats2half2_rn(msg.x, msg.y);
        }
    }
}

// ---------------- phase B: warp per DST node ----------------
__global__ void __launch_bounds__(256)
phaseB_kernel(const float* __restrict__ bias, float* __restrict__ h_out, int N) {
    int n    = (blockIdx.x * blockDim.x + threadIdx.x) >> 5;
    int lane = threadIdx.x & 31;
    if (n >= N) return;
    int beg = g_rowptr_d[n], end = g_rowptr_d[n + 1];

    const __half2* mp = (const __half2*)g_msg + lane;
    float2 acc = make_float2(0.f, 0.f);
#pragma unroll 4
    for (int e = beg; e < end; e++) {
        float2 v = __half22float2(__ldg(mp + (size_t)e * 32));
        acc.x += v.x;
        acc.y += v.y;
    }
    int   dg  = end - beg;
    float inv = 1.f / (float)(dg > 0 ? dg : 1);
    float2 rt = __ldg((const float2*)(g_root + (size_t)n * C) + lane);
    float2 bb = __ldg((const float2*)bias + lane);
    float2 res;
    res.x = fmaxf(acc.x * inv + rt.x + bb.x, 0.f);
    res.y = fmaxf(acc.y * inv + rt.y + bb.y, 0.f);
    ((float2*)h_out)[(size_t)n * 32 + lane] = res;
}

// ---------------- launch ----------------
extern "C" void kernel_launch(void* const* d_in, const int* in_sizes, int n_in,
                              void* d_out, int out_size) {
    const float* x     = (const float*)d_in[0];
    const int*   ei    = (const int*)d_in[1];
    const float* ea    = (const float*)d_in[2];
    const float* W0    = (const float*)d_in[3];
    const float* root0 = (const float*)d_in[4];
    const float* b0    = (const float*)d_in[5];
    const float* W1    = (const float*)d_in[6];
    const float* root1 = (const float*)d_in[7];
    const float* b1    = (const float*)d_in[8];
    const float* W2    = (const float*)d_in[9];
    const float* root2 = (const float*)d_in[10];
    const float* b2    = (const float*)d_in[11];
    float* out = (float*)d_out;

    int N = in_sizes[0] / 3;
    int E = in_sizes[1] / 2;
    const int* src = ei;
    const int* dst = ei + E;

    float* hP;
    cudaGetSymbolAddress((void**)&hP, g_h);

    int nodeBlocks = (N * 32 + 255) / 256;
    dim3 tGrid((N + T_NODES - 1) / T_NODES, MKER + 1);

    // ---- prepass: dual CSR + layer-0 scatter ----
    zeroAll_kernel<<<(N * SSTR + 255) / 256, 256>>>(N);
    hist2_kernel<<<(E + 255) / 256, 256>>>(src, dst, E);
    scan2_kernel<<<2, 1024>>>(N);
    build_kernel<<<(E + 255) / 256, 256>>>(src, dst, ea, x, E);

    // ---- layer 0 ----
    l0_kernel<<<nodeBlocks, 256>>>(x, W0, root0, b0, N);

    // ---- layer 1 ----
    transform_kernel<<<tGrid, 256>>>(hP, W1, root1, N);
    phaseA_kernel<<<nodeBlocks, 256>>>(N);
    phaseB_kernel<<<nodeBlocks, 256>>>(b1, hP, N);

    // ---- layer 2 ----
    transform_kernel<<<tGrid, 256>>>(hP, W2, root2, N);
    phaseA_kernel<<<nodeBlocks, 256>>>(N);
    phaseB_kernel<<<nodeBlocks, 256>>>(b2, out, N);
}

// round 10
// speedup vs baseline: 1.1082x; 1.1082x over previous
#include <cuda_runtime.h>
#include <cuda_fp16.h>

// ---------------- problem constants ----------------
#define NMAX 50000
#define EMAX 800000
#define MKER 27            // 3^3 spline kernels
#define C    64            // hidden channels
#define YSTR (MKER * C)    // 1728 halves per node
#define SSTR 108           // 27 * 4 (ci0,ci1,ci2,pad) layer-0 agg row

// ---------------- static scratch ----------------
__device__ __half g_y[(size_t)NMAX * YSTR];   // 172.8 MB transformed features (fp16)
__device__ float  g_root[NMAX * C];           // fp32 root-weight term h @ Wr
__device__ float  g_h[NMAX * C];              // hidden state (fp32)
__device__ float  g_S[NMAX * SSTR];           // layer-0 input-space agg (21.6 MB)
__device__ float4 g_rec[EMAX];                // CSR edge records: (src, ea0, ea1, ea2)
__device__ int    g_rowptr[NMAX + 1];
__device__ int    g_cursor[NMAX];
__device__ int    g_deg[NMAX];

// ---------------- helpers ----------------
__device__ __forceinline__ float2 ffma2(float2 a, float2 b, float2 c) {
    float2 d;
    asm("fma.rn.f32x2 %0, %1, %2, %3;"
        : "=l"(*reinterpret_cast<unsigned long long*>(&d))
        : "l"(*reinterpret_cast<unsigned long long*>(&a)),
          "l"(*reinterpret_cast<unsigned long long*>(&b)),
          "l"(*reinterpret_cast<unsigned long long*>(&c)));
    return d;
}

__device__ __forceinline__ void basis8(float e0, float e1, float e2,
                                       float w[8], int kk[8]) {
    float p0 = e0 * 2.0f, p1 = e1 * 2.0f, p2 = e2 * 2.0f;
    float f0 = fminf(fmaxf(floorf(p0), 0.f), 1.f);
    float f1 = fminf(fmaxf(floorf(p1), 0.f), 1.f);
    float f2 = fminf(fmaxf(floorf(p2), 0.f), 1.f);
    float u0 = p0 - f0, u1 = p1 - f1, u2 = p2 - f2;
    int base = (int)f0 + 3 * (int)f1 + 9 * (int)f2;
#pragma unroll
    for (int b = 0; b < 8; b++) {
        float a0 = (b & 1) ? u0 : 1.f - u0;
        float a1 = (b & 2) ? u1 : 1.f - u1;
        float a2 = (b & 4) ? u2 : 1.f - u2;
        w[b]  = a0 * a1 * a2;
        kk[b] = base + (b & 1) + 3 * ((b >> 1) & 1) + 9 * ((b >> 2) & 1);
    }
}

// ---------------- CSR build ----------------
__global__ void zeroAll_kernel(int N) {
    int i = blockIdx.x * blockDim.x + threadIdx.x;
    if (i < N * SSTR) g_S[i] = 0.f;
    if (i < N)        g_deg[i] = 0;
}
__global__ void hist_kernel(const int* __restrict__ dst, int E) {
    int i = blockIdx.x * blockDim.x + threadIdx.x;
    if (i < E) atomicAdd(&g_deg[dst[i]], 1);
}
// single-block exclusive scan of g_deg -> g_rowptr (and g_cursor copy)
__global__ void scan_kernel(int N) {
    __shared__ int ssum[1024];
    int tid = threadIdx.x;
    int chunk = (N + 1023) / 1024;
    int beg = tid * chunk;
    int end = min(beg + chunk, N);
    int s = 0;
    for (int i = beg; i < end; i++) s += g_deg[i];
    ssum[tid] = s;
    __syncthreads();
    for (int off = 1; off < 1024; off <<= 1) {
        int v = 0;
        if (tid >= off) v = ssum[tid - off];
        __syncthreads();
        if (tid >= off) ssum[tid] += v;
        __syncthreads();
    }
    int run = (tid == 0) ? 0 : ssum[tid - 1];
    for (int i = beg; i < end; i++) {
        g_rowptr[i] = run;
        g_cursor[i] = run;
        run += g_deg[i];
    }
    if (tid == 1023) g_rowptr[N] = ssum[1023];
}

// edge pass: write CSR record + layer-0 input-space scatter (float4 RED)
__global__ void build_kernel(const int* __restrict__ src,
                             const int* __restrict__ dst,
                             const float* __restrict__ ea,
                             const float* __restrict__ x, int E) {
    int e = blockIdx.x * blockDim.x + threadIdx.x;
    if (e >= E) return;
    int s = src[e], d = dst[e];
    float e0 = ea[3 * e], e1 = ea[3 * e + 1], e2 = ea[3 * e + 2];

    int pos = atomicAdd(&g_cursor[d], 1);
    g_rec[pos] = make_float4(__int_as_float(s), e0, e1, e2);

    float w[8]; int kk[8];
    basis8(e0, e1, e2, w, kk);
    float x0 = __ldg(x + 3 * s), x1 = __ldg(x + 3 * s + 1), x2 = __ldg(x + 3 * s + 2);
    float4* Sb = (float4*)(g_S + (size_t)d * SSTR);
#pragma unroll
    for (int c = 0; c < 8; c++)
        atomicAdd(Sb + kk[c], make_float4(w[c] * x0, w[c] * x1, w[c] * x2, 0.f));
}

// ---------------- layer 0 finalize: h = relu(S@W0/deg + x@root0 + b0) --------
__global__ void __launch_bounds__(256)
l0_kernel(const float* __restrict__ x, const float* __restrict__ W0,
          const float* __restrict__ root0, const float* __restrict__ b0, int N) {
    int n    = (blockIdx.x * blockDim.x + threadIdx.x) >> 5;
    int lane = threadIdx.x & 31;
    if (n >= N) return;
    const float* Sr = g_S + (size_t)n * SSTR;
    float sA = Sr[lane];
    float sB = Sr[32 + lane];
    float sC = Sr[64 + lane];
    float sD = (lane < 12) ? Sr[96 + lane] : 0.f;

    float2 acc = make_float2(0.f, 0.f);
#pragma unroll
    for (int m = 0; m < MKER; m++) {
#pragma unroll
        for (int ci = 0; ci < 3; ci++) {
            int s  = m * 4 + ci;
            int r  = s >> 5, sl = s & 31;
            float v = (r == 0) ? __shfl_sync(0xffffffffu, sA, sl)
                    : (r == 1) ? __shfl_sync(0xffffffffu, sB, sl)
                    : (r == 2) ? __shfl_sync(0xffffffffu, sC, sl)
                               : __shfl_sync(0xffffffffu, sD, sl);
            float2 wv = __ldg((const float2*)(W0 + (m * 3 + ci) * C) + lane);
            acc.x += v * wv.x;
            acc.y += v * wv.y;
        }
    }
    int   dg  = g_rowptr[n + 1] - g_rowptr[n];
    float inv = 1.f / (float)(dg > 0 ? dg : 1);
    float xv  = (lane < 3) ? __ldg(x + 3 * n + lane) : 0.f;
    float x0  = __shfl_sync(0xffffffffu, xv, 0);
    float x1  = __shfl_sync(0xffffffffu, xv, 1);
    float x2  = __shfl_sync(0xffffffffu, xv, 2);
    float2 r0 = __ldg((const float2*)(root0)         + lane);
    float2 r1 = __ldg((const float2*)(root0 + C)     + lane);
    float2 r2 = __ldg((const float2*)(root0 + 2 * C) + lane);
    float2 bb = __ldg((const float2*)(b0)            + lane);
    float2 res;
    res.x = fmaxf(acc.x * inv + x0 * r0.x + x1 * r1.x + x2 * r2.x + bb.x, 0.f);
    res.y = fmaxf(acc.y * inv + x0 * r0.y + x1 * r1.y + x2 * r2.y + bb.y, 0.f);
    ((float2*)g_h)[(size_t)n * 32 + lane] = res;
}

// ---------------- transform: y[n, m, co] = sum_ci h[n,ci] * W[m,ci,co] --------
// Conflict-free orientation:
//   - W kept in NATURAL [ci][co] smem layout: per-ci load is one LDS.32 with
//     consecutive-co lanes -> single 128B wavefront, zero conflicts.
//   - h transposed in smem (hsT[ci][n], pad 68): the fma2 vector lane is a
//     NODE PAIR, so (h[n],h[n+1]) falls out of a broadcast LDS.128 as an
//     aligned register pair -> no packing MOVs.
// Thread owns one co and 16 nodes; 8 fma2 per ci -> fma-pipe bound.
#define T_NODES 64
#define HT_STR  68
__global__ void __launch_bounds__(256)
transform_kernel(const float* __restrict__ h, const float* __restrict__ W,
                 const float* __restrict__ Wr, int N) {
    __shared__ float Wt[C * C];        // [ci][co] natural, 16 KB
    __shared__ float hsT[C * HT_STR];  // [ci][n] padded, 17 KB
    int m   = blockIdx.y;
    int n0  = blockIdx.x * T_NODES;
    int tid = threadIdx.x;

    const float* Wm = (m < MKER) ? (W + m * C * C) : Wr;
    for (int i = tid; i < C * C; i += 256)
        Wt[i] = Wm[i];
    for (int i = tid; i < T_NODES * C; i += 256) {
        int nl = i >> 6, ci = i & 63;
        int n  = n0 + nl;
        hsT[ci * HT_STR + nl] = (n < N) ? h[(size_t)n * C + ci] : 0.f;
    }
    __syncthreads();

    int co = tid & 63;
    int nb = (tid >> 6) * 16;          // 4 groups x 16 nodes

    float2 acc[8];
#pragma unroll
    for (int j = 0; j < 8; j++) acc[j] = make_float2(0.f, 0.f);

#pragma unroll 8
    for (int ci = 0; ci < C; ci++) {
        float  w  = Wt[ci * C + co];           // conflict-free LDS.32
        float2 wd = make_float2(w, w);
        const float4* hp = (const float4*)&hsT[ci * HT_STR + nb];
        float4 a = hp[0], b = hp[1], c = hp[2], d = hp[3];   // broadcast LDS.128
        acc[0] = ffma2(make_float2(a.x, a.y), wd, acc[0]);
        acc[1] = ffma2(make_float2(a.z, a.w), wd, acc[1]);
        acc[2] = ffma2(make_float2(b.x, b.y), wd, acc[2]);
        acc[3] = ffma2(make_float2(b.z, b.w), wd, acc[3]);
        acc[4] = ffma2(make_float2(c.x, c.y), wd, acc[4]);
        acc[5] = ffma2(make_float2(c.z, c.w), wd, acc[5]);
        acc[6] = ffma2(make_float2(d.x, d.y), wd, acc[6]);
        acc[7] = ffma2(make_float2(d.z, d.w), wd, acc[7]);
    }

#pragma unroll
    for (int j = 0; j < 8; j++) {
        int n = n0 + nb + 2 * j;
        if (n >= N) break;
        if (m < MKER) {
            g_y[(size_t)n * YSTR + m * C + co] = __float2half_rn(acc[j].x);
            if (n + 1 < N)
                g_y[(size_t)(n + 1) * YSTR + m * C + co] = __float2half_rn(acc[j].y);
        } else {
            g_root[(size_t)n * C + co] = acc[j].x;
            if (n + 1 < N)
                g_root[(size_t)(n + 1) * C + co] = acc[j].y;
        }
    }
}

// ---------------- node kernel (layers 1,2): warp per dst node ----------------
// CSR records staged via one coalesced float4 load per 32 edges; edge loop has
// no loop-carried memory dependence, so consecutive edges' gathers overlap.
__global__ void __launch_bounds__(256)
node_kernel(const float* __restrict__ bias, float* __restrict__ h_out, int N) {
    __shared__ float4 recs[8][32];
    int wid  = threadIdx.x >> 5;
    int lane = threadIdx.x & 31;
    int n    = (blockIdx.x * blockDim.x + threadIdx.x) >> 5;
    if (n >= N) return;
    int beg = g_rowptr[n], end = g_rowptr[n + 1];

    float2 acc = make_float2(0.f, 0.f);
    for (int base = beg; base < end; base += 32) {
        int cnt = min(32, end - base);
        __syncwarp();
        if (lane < cnt) recs[wid][lane] = __ldg(&g_rec[base + lane]);
        __syncwarp();
#pragma unroll 4
        for (int e = 0; e < cnt; e++) {
            float4 r = recs[wid][e];                 // LDS broadcast
            int s = __float_as_int(r.x);
            float w[8]; int kk[8];
            basis8(r.y, r.z, r.w, w, kk);
            const __half* yb = g_y + (size_t)s * YSTR;
#pragma unroll
            for (int c = 0; c < 8; c++) {
                __half2 hv = __ldg((const __half2*)(yb + kk[c] * C) + lane);
                float2 v = __half22float2(hv);
                acc.x += w[c] * v.x;
                acc.y += w[c] * v.y;
            }
        }
    }
    int   dg  = end - beg;
    float inv = 1.f / (float)(dg > 0 ? dg : 1);
    float2 rt = __ldg((const float2*)(g_root + (size_t)n * C) + lane);
    float2 bb = __ldg((const float2*)bias + lane);
    float2 res;
    res.x = fmaxf(acc.x * inv + rt.x + bb.x, 0.f);
    res.y = fmaxf(acc.y * inv + rt.y + bb.y, 0.f);
    ((float2*)h_out)[(size_t)n * 32 + lane] = res;
}

// ---------------- launch ----------------
extern "C" void kernel_launch(void* const* d_in, const int* in_sizes, int n_in,
                              void* d_out, int out_size) {
    const float* x     = (const float*)d_in[0];
    const int*   ei    = (const int*)d_in[1];
    const float* ea    = (const float*)d_in[2];
    const float* W0    = (const float*)d_in[3];
    const float* root0 = (const float*)d_in[4];
    const float* b0    = (const float*)d_in[5];
    const float* W1    = (const float*)d_in[6];
    const float* root1 = (const float*)d_in[7];
    const float* b1    = (const float*)d_in[8];
    const float* W2    = (const float*)d_in[9];
    const float* root2 = (const float*)d_in[10];
    const float* b2    = (const float*)d_in[11];
    float* out = (float*)d_out;

    int N = in_sizes[0] / 3;
    int E = in_sizes[1] / 2;
    const int* src = ei;
    const int* dst = ei + E;

    float* hP;
    cudaGetSymbolAddress((void**)&hP, g_h);

    int nodeBlocks = (N * 32 + 255) / 256;
    dim3 tGrid((N + T_NODES - 1) / T_NODES, MKER + 1);

    // ---- CSR + layer-0 scatter ----
    zeroAll_kernel<<<(N * SSTR + 255) / 256, 256>>>(N);
    hist_kernel<<<(E + 255) / 256, 256>>>(dst, E);
    scan_kernel<<<1, 1024>>>(N);
    build_kernel<<<(E + 255) / 256, 256>>>(src, dst, ea, x, E);

    // ---- layer 0 ----
    l0_kernel<<<nodeBlocks, 256>>>(x, W0, root0, b0, N);

    // ---- layer 1 ----
    transform_kernel<<<tGrid, 256>>>(hP, W1, root1, N);
    node_kernel<<<nodeBlocks, 256>>>(b1, hP, N);

    // ---- layer 2 ----
    transform_kernel<<<tGrid, 256>>>(hP, W2, root2, N);
    node_kernel<<<nodeBlocks, 256>>>(b2, out, N);
}